// round 13
// baseline (speedup 1.0000x reference)
#include <cuda_runtime.h>

typedef unsigned long long u64;

// ---------- packed f32x2 helpers (sm_103a FFMA2 only via PTX) ----------
__device__ __forceinline__ u64 pack2(float lo, float hi){
    u64 r; asm("mov.b64 %0, {%1,%2};" : "=l"(r) : "f"(lo), "f"(hi)); return r;
}
__device__ __forceinline__ void unpack2(u64 v, float &lo, float &hi){
    asm("mov.b64 {%0,%1}, %2;" : "=f"(lo), "=f"(hi) : "l"(v));
}
__device__ __forceinline__ u64 mul2(u64 a, u64 b){
    u64 r; asm("mul.rn.f32x2 %0, %1, %2;" : "=l"(r) : "l"(a), "l"(b)); return r;
}
__device__ __forceinline__ void fma2(u64 &d, u64 a, u64 b){
    asm("fma.rn.f32x2 %0, %1, %2, %0;" : "+l"(d) : "l"(a), "l"(b));
}

// ---------- symmetrized coefficient tables ----------------------------------
// prep writes the global copies; kernel_launch memcpys them into __constant__
// (warp-uniform indices -> const-port broadcast, NO per-lane L1 replication).
__device__ __align__(16) u64 g_C1[9 * 4];
__device__ __align__(16) u64 g_C2[45 * 8];
__device__ __align__(16) u64 g_C3[165 * 16];   // padded: col c at (c/3)*4 + c%3

__constant__ __align__(16) u64 c_C1[9 * 4];
__constant__ __align__(16) u64 c_C2[45 * 8];
__constant__ __align__(16) u64 c_C3[165 * 16];

__device__ __forceinline__ float fetch3(const float* __restrict__ b30,
                                        const float* __restrict__ b31,
                                        int i, int j, int k, int c){
    int base = ((i * 9 + j) * 9 + k) * 3;         // b30: (9,9,9,3,1); b31: (9,9,9,3,3)
    if (c < 3) return b30[base + c];
    return b31[base * 3 + (c - 3)];
}

__global__ void prep_kernel(const float* __restrict__ b10, const float* __restrict__ b11,
                            const float* __restrict__ b20, const float* __restrict__ b21,
                            const float* __restrict__ b30, const float* __restrict__ b31){
    int tid = blockIdx.x * blockDim.x + threadIdx.x;

    if (tid < 36){
        int a = tid >> 2, c = tid & 3;
        float v = (c == 0) ? b10[a] : b11[a * 3 + c - 1];
        g_C1[tid] = pack2(v, v);
    }

    int t2 = tid - 64;
    if (t2 >= 0 && t2 < 45 * 8){
        int mono = t2 >> 3, c = t2 & 7;
        int a = 0, rem = mono;
        while (rem >= 9 - a){ rem -= 9 - a; a++; }
        int b = a + rem;                            // a <= b
        float v;
        if (c < 2){                                 // b20: (9,9,2,1)
            v = b20[(a * 9 + b) * 2 + c];
            if (a != b) v += b20[(b * 9 + a) * 2 + c];
        } else {                                    // b21: (9,9,2,3); c-2 = s*3+p
            int sp = c - 2;
            v = b21[(a * 9 + b) * 6 + sp];
            if (a != b) v += b21[(b * 9 + a) * 6 + sp];
        }
        g_C2[t2] = pack2(v, v);
    }

    int t3 = tid - 448;
    if (t3 >= 0 && t3 < 165 * 12){
        int mono = t3 / 12, c = t3 % 12;
        int a = 0, rem = mono;
        while (true){ int cnt = (9 - a) * (10 - a) / 2; if (rem < cnt) break; rem -= cnt; a++; }
        int b = a;
        while (rem >= 9 - b){ rem -= 9 - b; b++; }
        int k = b + rem;                            // a <= b <= k
        float v = fetch3(b30, b31, a, b, k, c);
        if (a == b && b == k){
        } else if (a == b){
            v += fetch3(b30, b31, a, k, b, c) + fetch3(b30, b31, k, a, b, c);
        } else if (b == k){
            v += fetch3(b30, b31, b, a, k, c) + fetch3(b30, b31, b, k, a, c);
        } else {
            v += fetch3(b30, b31, a, k, b, c) + fetch3(b30, b31, b, a, k, c)
               + fetch3(b30, b31, b, k, a, c) + fetch3(b30, b31, k, a, b, c)
               + fetch3(b30, b31, k, b, a, c);
        }
        g_C3[mono * 16 + (c / 3) * 4 + (c % 3)] = pack2(v, v);
    }
}

// ---------- main kernel ------------------------------------------------------
// 1 block = 1 node, 128 threads = 4 warps. Warp id = colQ (warp-uniform column
// quarter -> const-port broadcast loads); lane = channel quad, 4 ch/thread.
//   colQ: C1 col colQ | C2 cols 2colQ..2colQ+1 | C3 cols 3colQ..3colQ+2
// Coefficients come from __constant__ -> zero L1 data traffic for them;
// no smem table staging, no startup sync.
__global__ void __launch_bounds__(128) mace_kernel(
    const float* __restrict__ nf, const int* __restrict__ species,
    const float* __restrict__ w10, const float* __restrict__ w11,
    const float* __restrict__ w20, const float* __restrict__ w21,
    const float* __restrict__ w30, const float* __restrict__ w31,
    float* __restrict__ out)
{
    __shared__ float part[3][512];          // partials from colQ 1..3

    const int t    = threadIdx.x;
    const int node = blockIdx.x;
    const int colQ = t >> 5;              // warp-uniform column quarter [0,4)
    const int lane = t & 31;
    const int m0   = lane * 4;            // channels m0..m0+3 (pair A, pair B)
    const float* nfp = nf + (size_t)node * 1152;

    // x components fully in registers.
    u64 xA[9], xB[9];
    {
        float4 v = *(const float4*)(nfp + m0);
        xA[0] = pack2(v.x, v.y);
        xB[0] = pack2(v.z, v.w);
    }
    #pragma unroll
    for (int j = 0; j < 3; j++){
        xA[1 + j] = pack2(nfp[128 + m0 * 3 + j],      nfp[128 + m0 * 3 + 3 + j]);
        xB[1 + j] = pack2(nfp[128 + m0 * 3 + 6 + j],  nfp[128 + m0 * 3 + 9 + j]);
    }
    #pragma unroll
    for (int j = 0; j < 5; j++){
        xA[4 + j] = pack2(nfp[512 + m0 * 5 + j],      nfp[512 + m0 * 5 + 5 + j]);
        xB[4 + j] = pack2(nfp[512 + m0 * 5 + 10 + j], nfp[512 + m0 * 5 + 15 + j]);
    }

    // Per-thread accumulators: P1 (C1 col), P2[2] (C2 cols), P3[3] (C3 cols)
    u64 P1A = 0ull, P1B = 0ull;
    u64 P2A[2] = {0ull, 0ull}, P2B[2] = {0ull, 0ull};
    u64 P3A[3] = {0ull, 0ull, 0ull}, P3B[3] = {0ull, 0ull, 0ull};

    const int o2 = colQ * 2;              // warp-uniform offsets
    const int o3 = colQ * 4;

    int i2 = 0, i3 = 0;                       // constant-folded by full unroll
    #pragma unroll
    for (int a = 0; a < 9; a++){
        {
            u64 c = c_C1[a * 4 + colQ];
            fma2(P1A, c, xA[a]);  fma2(P1B, c, xB[a]);
        }
        #pragma unroll
        for (int b = a; b < 9; b++){
            u64 pabA = mul2(xA[a], xA[b]);
            u64 pabB = mul2(xB[a], xB[b]);
            {
                ulonglong2 c = *(const ulonglong2*)&c_C2[i2 * 8 + o2];
                fma2(P2A[0], c.x, pabA);  fma2(P2B[0], c.x, pabB);
                fma2(P2A[1], c.y, pabA);  fma2(P2B[1], c.y, pabB);
            }
            i2++;
            #pragma unroll
            for (int k = b; k < 9; k++){
                u64 p3A = mul2(pabA, xA[k]);
                u64 p3B = mul2(pabB, xB[k]);
                ulonglong2 c01 = *(const ulonglong2*)&c_C3[i3 * 16 + o3];
                u64 c2v = c_C3[i3 * 16 + o3 + 2];
                fma2(P3A[0], c01.x, p3A);  fma2(P3B[0], c01.x, p3B);
                fma2(P3A[1], c01.y, p3A);  fma2(P3B[1], c01.y, p3B);
                fma2(P3A[2], c2v,  p3A);   fma2(P3B[2], c2v,  p3B);
                i3++;
            }
        }
    }

    // ---- fold with per-(species, channel) weights (mapping verified R8/R10) -
    const int sp = species[node];
    const float* W10 = w10 + sp * 128;
    const float* W11 = w11 + sp * 128;
    const float* W20 = w20 + sp * 256;
    const float* W21 = w21 + sp * 256;
    const float* W30 = w30 + sp * 384;
    const float* W31 = w31 + sp * 384;

    u64 O0[2]  = {0ull, 0ull};
    u64 OP0[2] = {0ull, 0ull}, OP1[2] = {0ull, 0ull}, OP2[2] = {0ull, 0ull};

    #pragma unroll
    for (int h = 0; h < 2; h++){
        const int mc = m0 + 2 * h;
        u64 p1 = h ? P1B : P1A;
        u64* p2 = h ? P2B : P2A;
        u64* p3 = h ? P3B : P3A;
        if (colQ == 0){
            fma2(O0[h], *(const u64*)(W10 + mc),       p1);
            fma2(O0[h], *(const u64*)(W20 + mc),       p2[0]);
            fma2(O0[h], *(const u64*)(W20 + 128 + mc), p2[1]);
            fma2(O0[h], *(const u64*)(W30 + mc),       p3[0]);
            fma2(O0[h], *(const u64*)(W30 + 128 + mc), p3[1]);
            fma2(O0[h], *(const u64*)(W30 + 256 + mc), p3[2]);
        } else if (colQ == 1){
            fma2(OP0[h], *(const u64*)(W11 + mc),       p1);
            fma2(OP0[h], *(const u64*)(W21 + mc),       p2[0]);
            fma2(OP1[h], *(const u64*)(W21 + mc),       p2[1]);
            fma2(OP0[h], *(const u64*)(W31 + mc),       p3[0]);
            fma2(OP1[h], *(const u64*)(W31 + mc),       p3[1]);
            fma2(OP2[h], *(const u64*)(W31 + mc),       p3[2]);
        } else if (colQ == 2){
            fma2(OP1[h], *(const u64*)(W11 + mc),       p1);
            fma2(OP2[h], *(const u64*)(W21 + mc),       p2[0]);
            fma2(OP0[h], *(const u64*)(W21 + 128 + mc), p2[1]);
            fma2(OP0[h], *(const u64*)(W31 + 128 + mc), p3[0]);
            fma2(OP1[h], *(const u64*)(W31 + 128 + mc), p3[1]);
            fma2(OP2[h], *(const u64*)(W31 + 128 + mc), p3[2]);
        } else {
            fma2(OP2[h], *(const u64*)(W11 + mc),       p1);
            fma2(OP1[h], *(const u64*)(W21 + 128 + mc), p2[0]);
            fma2(OP2[h], *(const u64*)(W21 + 128 + mc), p2[1]);
            fma2(OP0[h], *(const u64*)(W31 + 256 + mc), p3[0]);
            fma2(OP1[h], *(const u64*)(W31 + 256 + mc), p3[1]);
            fma2(OP2[h], *(const u64*)(W31 + 256 + mc), p3[2]);
        }
    }

    // ---- combine quarters through smem, colQ-0 warp stores -------------------
    float r[16];  // [h][acc: O0,OP0,OP1,OP2][lo/hi]
    #pragma unroll
    for (int h = 0; h < 2; h++){
        unpack2(O0[h],  r[h*8+0], r[h*8+1]);
        unpack2(OP0[h], r[h*8+2], r[h*8+3]);
        unpack2(OP1[h], r[h*8+4], r[h*8+5]);
        unpack2(OP2[h], r[h*8+6], r[h*8+7]);
    }

    if (colQ != 0){
        float* p = part[colQ - 1];
        p[m0 + 0] = r[0];  p[m0 + 1] = r[1];
        p[m0 + 2] = r[8];  p[m0 + 3] = r[9];
        #pragma unroll
        for (int h = 0; h < 2; h++){
            const int mc = m0 + 2 * h;
            p[128 + mc * 3 + 0] = r[h*8+2];  p[128 + mc * 3 + 3] = r[h*8+3];
            p[128 + mc * 3 + 1] = r[h*8+4];  p[128 + mc * 3 + 4] = r[h*8+5];
            p[128 + mc * 3 + 2] = r[h*8+6];  p[128 + mc * 3 + 5] = r[h*8+7];
        }
    }
    __syncthreads();
    if (colQ == 0){
        float* outp = out + (size_t)node * 512;
        float s0 = r[0], s1 = r[1], s2 = r[8], s3 = r[9];
        #pragma unroll
        for (int j = 0; j < 3; j++){
            const float* p = part[j];
            s0 += p[m0 + 0];  s1 += p[m0 + 1];
            s2 += p[m0 + 2];  s3 += p[m0 + 3];
        }
        *(float4*)(outp + m0) = make_float4(s0, s1, s2, s3);

        #pragma unroll
        for (int h = 0; h < 2; h++){
            const int mc = m0 + 2 * h;
            float v0 = r[h*8+2], v3 = r[h*8+3];
            float v1 = r[h*8+4], v4 = r[h*8+5];
            float v2 = r[h*8+6], v5 = r[h*8+7];
            #pragma unroll
            for (int j = 0; j < 3; j++){
                const float* p = part[j];
                v0 += p[128 + mc * 3 + 0];  v3 += p[128 + mc * 3 + 3];
                v1 += p[128 + mc * 3 + 1];  v4 += p[128 + mc * 3 + 4];
                v2 += p[128 + mc * 3 + 2];  v5 += p[128 + mc * 3 + 5];
            }
            outp[128 + mc * 3 + 0] = v0;  outp[128 + mc * 3 + 3] = v3;
            outp[128 + mc * 3 + 1] = v1;  outp[128 + mc * 3 + 4] = v4;
            outp[128 + mc * 3 + 2] = v2;  outp[128 + mc * 3 + 5] = v5;
        }
    }
}

extern "C" void kernel_launch(void* const* d_in, const int* in_sizes, int n_in,
                              void* d_out, int out_size){
    // metadata order is INTERLEAVED (b_i, w_i) pairs.
    const float* nf      = (const float*)d_in[0];
    const int*   species = (const int*)  d_in[1];
    const float* b10 = (const float*)d_in[2];
    const float* w10 = (const float*)d_in[3];
    const float* b11 = (const float*)d_in[4];
    const float* w11 = (const float*)d_in[5];
    const float* b20 = (const float*)d_in[6];
    const float* w20 = (const float*)d_in[7];
    const float* b21 = (const float*)d_in[8];
    const float* w21 = (const float*)d_in[9];
    const float* b30 = (const float*)d_in[10];
    const float* w30 = (const float*)d_in[11];
    const float* b31 = (const float*)d_in[12];
    const float* w31 = (const float*)d_in[13];

    const int n_nodes = in_sizes[1];   // species element count (2048)

    // 1) symmetrize bases into global tables
    prep_kernel<<<19, 128>>>(b10, b11, b20, b21, b30, b31);

    // 2) stage tables into __constant__ (async D2D memcpy nodes — capturable)
    void* gC1; cudaGetSymbolAddress(&gC1, g_C1);
    void* gC2; cudaGetSymbolAddress(&gC2, g_C2);
    void* gC3; cudaGetSymbolAddress(&gC3, g_C3);
    cudaMemcpyToSymbolAsync(c_C1, gC1, sizeof(g_C1), 0, cudaMemcpyDeviceToDevice, 0);
    cudaMemcpyToSymbolAsync(c_C2, gC2, sizeof(g_C2), 0, cudaMemcpyDeviceToDevice, 0);
    cudaMemcpyToSymbolAsync(c_C3, gC3, sizeof(g_C3), 0, cudaMemcpyDeviceToDevice, 0);

    // 3) main kernel: 1 block = 1 node, 4 warp-uniform column quarters
    mace_kernel<<<n_nodes, 128>>>(nf, species, w10, w11, w20, w21, w30, w31,
                                  (float*)d_out);
}

// round 15
// speedup vs baseline: 2.0080x; 2.0080x over previous
#include <cuda_runtime.h>
#include <cuda_bf16.h>
#include <cstdint>

typedef unsigned long long u64;

// pack two fp32 -> bf16x2 (first arg -> low half, second -> high half)
__device__ __forceinline__ uint32_t packbf(float lo, float hi){
    uint32_t r;
    asm("cvt.rn.bf16x2.f32 %0, %2, %1;" : "=r"(r) : "f"(lo), "f"(hi));
    return r;
}
__device__ __forceinline__ uint32_t smem_to_u32(const void* p){
    uint32_t a;
    asm("{ .reg .u64 t; cvta.to.shared.u64 t, %1; cvt.u32.u64 %0, t; }"
        : "=r"(a) : "l"(p));
    return a;
}
#define LDSM_X4(r, addr) \
    asm volatile("ldmatrix.sync.aligned.m8n8.x4.shared.b16 {%0,%1,%2,%3}, [%4];" \
        : "=r"((r)[0]), "=r"((r)[1]), "=r"((r)[2]), "=r"((r)[3]) : "r"(addr))
#define MMA16816(d, a, b0, b1) \
    asm volatile("mma.sync.aligned.m16n8k16.row.col.f32.bf16.bf16.f32 " \
        "{%0,%1,%2,%3}, {%4,%5,%6,%7}, {%8,%9}, {%0,%1,%2,%3};" \
        : "+f"((d)[0]), "+f"((d)[1]), "+f"((d)[2]), "+f"((d)[3]) \
        : "r"((a)[0]), "r"((a)[1]), "r"((a)[2]), "r"((a)[3]), "r"(b0), "r"(b1))

// ======================= B in mma-fragment order ============================
// B[m (mono, K), n (output col, 24 used of 32)], bf16.
// K sections: [0,224)=Chi, [224,448)=Clo, [448,672)=Chi(again, for Xlo term).
// Fragment table: [j=42 chunks][nt=3 n-tiles][lane=32][reg=2] u32 (bf16x2).
//   reg0 = B[kb+(lane%4)*2 +{0,1}][nt*8+lane/4], reg1 = same +{8,9}.
__device__ uint32_t g_Bfrag[42 * 3 * 32 * 2];

__device__ __forceinline__ float fetch3(const float* __restrict__ b30,
                                        const float* __restrict__ b31,
                                        int i, int j, int k, int c){
    int base = ((i * 9 + j) * 9 + k) * 3;
    if (c < 3) return b30[base + c];
    return b31[base * 3 + (c - 3)];
}

__device__ float coef(int m, int n,
                      const float* b10, const float* b11,
                      const float* b20, const float* b21,
                      const float* b30, const float* b31){
    if (m >= 219 || n >= 24) return 0.0f;
    if (m < 9){                               // deg1 -> cols 0..3
        if (n >= 4) return 0.0f;
        return (n == 0) ? b10[m] : b11[m * 3 + (n - 1)];
    }
    if (m < 54){                              // deg2 -> cols 4..11
        if (n < 4 || n >= 12) return 0.0f;
        int m2 = m - 9, a = 0, rem = m2;
        while (rem >= 9 - a){ rem -= 9 - a; a++; }
        int b = a + rem;
        int c2 = n - 4;
        float v;
        if (c2 < 2){
            v = b20[(a * 9 + b) * 2 + c2];
            if (a != b) v += b20[(b * 9 + a) * 2 + c2];
        } else {
            int sp = c2 - 2;
            v = b21[(a * 9 + b) * 6 + sp];
            if (a != b) v += b21[(b * 9 + a) * 6 + sp];
        }
        return v;
    }
    // deg3 -> cols 12..23
    if (n < 12) return 0.0f;
    int m3 = m - 54, a = 0, rem = m3;
    while (true){ int cnt = (9 - a) * (10 - a) / 2; if (rem < cnt) break; rem -= cnt; a++; }
    int b = a;
    while (rem >= 9 - b){ rem -= 9 - b; b++; }
    int kk = b + rem;
    int c3 = n - 12;
    float v = fetch3(b30, b31, a, b, kk, c3);
    if (a == b && b == kk){
    } else if (a == b){
        v += fetch3(b30, b31, a, kk, b, c3) + fetch3(b30, b31, kk, a, b, c3);
    } else if (b == kk){
        v += fetch3(b30, b31, b, a, kk, c3) + fetch3(b30, b31, b, kk, a, c3);
    } else {
        v += fetch3(b30, b31, a, kk, b, c3) + fetch3(b30, b31, b, a, kk, c3)
           + fetch3(b30, b31, b, kk, a, c3) + fetch3(b30, b31, kk, a, b, c3)
           + fetch3(b30, b31, kk, b, a, c3);
    }
    return v;
}

__global__ void prep_kernel(const float* __restrict__ b10, const float* __restrict__ b11,
                            const float* __restrict__ b20, const float* __restrict__ b21,
                            const float* __restrict__ b30, const float* __restrict__ b31){
    int id = blockIdx.x * blockDim.x + threadIdx.x;
    if (id >= 42 * 3 * 32 * 2) return;
    int reg  = id & 1;
    int lane = (id >> 1) & 31;
    int ntj  = id >> 6;
    int nt   = ntj % 3;
    int j    = ntj / 3;
    int sec  = j / 14;
    int kb   = (j - sec * 14) * 16;
    int n    = nt * 8 + (lane >> 2);
    int m0   = kb + (lane & 3) * 2 + reg * 8;

    float c0 = coef(m0,     n, b10, b11, b20, b21, b30, b31);
    float c1 = coef(m0 + 1, n, b10, b11, b20, b21, b30, b31);
    if (sec == 1){   // Clo section: residual after bf16 rounding
        c0 = c0 - __bfloat162float(__float2bfloat16_rn(c0));
        c1 = c1 - __bfloat162float(__float2bfloat16_rn(c1));
    }
    g_Bfrag[id] = packbf(c0, c1);
}

// ======================= main kernel: 1 block = 1 node ======================
// 128 threads. Phase 1 (thread = channel): compute 219 monomials, split hi/lo
// bf16, store to smem X [128 rows x 912B stride] (hi cols 0..223, lo 224..447).
// Phase 2 (warp = 32 channels): D[32,24] += sum over 42 K=16 chunks of
// mma.sync m16n8k16 (A via ldmatrix.x4 from X, B via LDS.64 fragment table).
// Phase 3: redistribute D via smem, per-channel weight fold, store.
__global__ void __launch_bounds__(128) mace_kernel(
    const float* __restrict__ nf, const int* __restrict__ species,
    const float* __restrict__ w10, const float* __restrict__ w11,
    const float* __restrict__ w20, const float* __restrict__ w21,
    const float* __restrict__ w30, const float* __restrict__ w31,
    float* __restrict__ out)
{
    extern __shared__ __align__(16) char sm[];
    // layout: [0, 32256) B fragment table; [32256, 32256+116736) X buffer
    char* smB = sm;
    char* smX = sm + 32256;
    const uint32_t xb_u32 = smem_to_u32(smX);

    const int tid  = threadIdx.x;
    const int node = blockIdx.x;

    // ---- copy B fragment table (32256 B = 2016 uint4) ----
    for (int i = tid; i < 2016; i += 128)
        ((uint4*)smB)[i] = ((const uint4*)g_Bfrag)[i];

    // ---- phase 1: monomials -> smem (hi & lo bf16) ----
    {
        const int ch = tid;
        const float* nfp = nf + (size_t)node * 1152;
        float xv[9];
        xv[0] = nfp[ch];
        #pragma unroll
        for (int j = 0; j < 3; j++) xv[1 + j] = nfp[128 + ch * 3 + j];
        #pragma unroll
        for (int j = 0; j < 5; j++) xv[4 + j] = nfp[512 + ch * 5 + j];

        uint32_t hb[4], lb[4];
        float ev = 0.f, er = 0.f;
        int s = 0;
        char* rowp = smX + (size_t)ch * 912;
        auto emit = [&](float v){
            float hi = __bfloat162float(__float2bfloat16_rn(v));
            float r  = v - hi;
            if (s & 1){
                int q = (s & 7) >> 1;
                hb[q] = packbf(ev, v);
                lb[q] = packbf(er, r);
                if ((s & 7) == 7){
                    int colb = s - 7;
                    *(uint4*)(rowp + colb * 2)       = make_uint4(hb[0], hb[1], hb[2], hb[3]);
                    *(uint4*)(rowp + 448 + colb * 2) = make_uint4(lb[0], lb[1], lb[2], lb[3]);
                }
            } else { ev = v; er = r; }
            s++;
        };
        #pragma unroll
        for (int a = 0; a < 9; a++) emit(xv[a]);
        #pragma unroll
        for (int a = 0; a < 9; a++)
            #pragma unroll
            for (int b = a; b < 9; b++) emit(xv[a] * xv[b]);
        #pragma unroll
        for (int a = 0; a < 9; a++)
            #pragma unroll
            for (int b = a; b < 9; b++){
                float pab = xv[a] * xv[b];
                #pragma unroll
                for (int k = b; k < 9; k++) emit(pab * xv[k]);
            }
        #pragma unroll
        for (int z = 0; z < 5; z++) emit(0.0f);   // pad 219 -> 224
    }
    __syncthreads();

    // ---- phase 2: tensor-core contraction ----
    const int lane = tid & 31;
    const int wrp  = tid >> 5;
    const int R    = wrp * 32;

    float d[2][3][4];
    #pragma unroll
    for (int mt = 0; mt < 2; mt++)
        #pragma unroll
        for (int nt = 0; nt < 3; nt++)
            #pragma unroll
            for (int q = 0; q < 4; q++) d[mt][nt][q] = 0.0f;

    // ldmatrix lane address: row = R + mt*16 + (lane&15), colgroup = (lane>>4)*8
    const uint32_t arow = xb_u32
        + (uint32_t)(R + (lane & 15)) * 912u
        + (uint32_t)((lane >> 4) * 8) * 2u;
    const u64* bfr = (const u64*)smB;

    for (int j = 0; j < 42; j++){
        int sec  = j / 14;
        int colb = (j - sec * 14) * 16 + (sec == 2 ? 224 : 0);
        uint32_t a0[4], a1[4];
        uint32_t ad = arow + (uint32_t)colb * 2u;
        LDSM_X4(a0, ad);
        LDSM_X4(a1, ad + 16u * 912u);

        #pragma unroll
        for (int nt = 0; nt < 3; nt++){
            u64 bv = bfr[(j * 3 + nt) * 32 + lane];
            uint32_t b0 = (uint32_t)bv, b1 = (uint32_t)(bv >> 32);
            MMA16816(d[0][nt], a0, b0, b1);
            MMA16816(d[1][nt], a1, b0, b1);
        }
    }
    __syncthreads();

    // ---- phase 3a: write D fragments to moments buffer (reuse X region) ----
    float* mom = (float*)smX;   // [128][24]
    #pragma unroll
    for (int mt = 0; mt < 2; mt++){
        int r0 = R + mt * 16 + (lane >> 2);
        int c0 = (lane & 3) * 2;
        #pragma unroll
        for (int nt = 0; nt < 3; nt++){
            int cc = nt * 8 + c0;
            mom[r0 * 24 + cc]           = d[mt][nt][0];
            mom[r0 * 24 + cc + 1]       = d[mt][nt][1];
            mom[(r0 + 8) * 24 + cc]     = d[mt][nt][2];
            mom[(r0 + 8) * 24 + cc + 1] = d[mt][nt][3];
        }
    }
    __syncthreads();

    // ---- phase 3b: per-channel weight fold ----
    {
        const int ch = tid;
        const int sp = species[node];
        float M[24];
        #pragma unroll
        for (int i = 0; i < 6; i++){
            float4 v = ((const float4*)(mom + ch * 24))[i];
            M[i * 4 + 0] = v.x; M[i * 4 + 1] = v.y;
            M[i * 4 + 2] = v.z; M[i * 4 + 3] = v.w;
        }
        float* outp = out + (size_t)node * 512;
        outp[ch] = w10[sp * 128 + ch]       * M[0]
                 + w20[sp * 256 + ch]       * M[4]
                 + w20[sp * 256 + 128 + ch] * M[5]
                 + w30[sp * 384 + ch]       * M[12]
                 + w30[sp * 384 + 128 + ch] * M[13]
                 + w30[sp * 384 + 256 + ch] * M[14];

        float w11v = w11[sp * 128 + ch];
        float w21a = w21[sp * 256 + ch],      w21b = w21[sp * 256 + 128 + ch];
        float w31a = w31[sp * 384 + ch],      w31b = w31[sp * 384 + 128 + ch];
        float w31c = w31[sp * 384 + 256 + ch];
        #pragma unroll
        for (int p = 0; p < 3; p++){
            outp[128 + ch * 3 + p] = w11v * M[1 + p]
                                   + w21a * M[6 + p]  + w21b * M[9 + p]
                                   + w31a * M[15 + p] + w31b * M[18 + p]
                                   + w31c * M[21 + p];
        }
    }
}

extern "C" void kernel_launch(void* const* d_in, const int* in_sizes, int n_in,
                              void* d_out, int out_size){
    // metadata order is INTERLEAVED (b_i, w_i) pairs.
    const float* nf      = (const float*)d_in[0];
    const int*   species = (const int*)  d_in[1];
    const float* b10 = (const float*)d_in[2];
    const float* w10 = (const float*)d_in[3];
    const float* b11 = (const float*)d_in[4];
    const float* w11 = (const float*)d_in[5];
    const float* b20 = (const float*)d_in[6];
    const float* w20 = (const float*)d_in[7];
    const float* b21 = (const float*)d_in[8];
    const float* w21 = (const float*)d_in[9];
    const float* b30 = (const float*)d_in[10];
    const float* w30 = (const float*)d_in[11];
    const float* b31 = (const float*)d_in[12];
    const float* w31 = (const float*)d_in[13];

    const int n_nodes = in_sizes[1];   // 2048

    const int smem_bytes = 32256 + 116736;   // B frags + X buffer = 148992
    static bool attr_set = false;
    cudaFuncSetAttribute(mace_kernel,
                         cudaFuncAttributeMaxDynamicSharedMemorySize, smem_bytes);
    (void)attr_set;

    // build B fragment table (hi/lo compensated, mma fragment order)
    prep_kernel<<<63, 128>>>(b10, b11, b20, b21, b30, b31);
    // per-node tensor-core contraction
    mace_kernel<<<n_nodes, 128, smem_bytes>>>(nf, species,
                                              w10, w11, w20, w21, w30, w31,
                                              (float*)d_out);
}

// round 16
// speedup vs baseline: 2.6000x; 1.2948x over previous
#include <cuda_runtime.h>
#include <cuda_bf16.h>
#include <cstdint>

typedef unsigned long long u64;

// pack two fp32 -> bf16x2 (first arg -> low half, second -> high half)
__device__ __forceinline__ uint32_t packbf(float lo, float hi){
    uint32_t r;
    asm("cvt.rn.bf16x2.f32 %0, %2, %1;" : "=r"(r) : "f"(lo), "f"(hi));
    return r;
}
__device__ __forceinline__ uint32_t smem_to_u32(const void* p){
    uint32_t a;
    asm("{ .reg .u64 t; cvta.to.shared.u64 t, %1; cvt.u32.u64 %0, t; }"
        : "=r"(a) : "l"(p));
    return a;
}
#define LDSM_X4(r, addr) \
    asm volatile("ldmatrix.sync.aligned.m8n8.x4.shared.b16 {%0,%1,%2,%3}, [%4];" \
        : "=r"((r)[0]), "=r"((r)[1]), "=r"((r)[2]), "=r"((r)[3]) : "r"(addr))
#define MMA16816(d, a, b0, b1) \
    asm volatile("mma.sync.aligned.m16n8k16.row.col.f32.bf16.bf16.f32 " \
        "{%0,%1,%2,%3}, {%4,%5,%6,%7}, {%8,%9}, {%0,%1,%2,%3};" \
        : "+f"((d)[0]), "+f"((d)[1]), "+f"((d)[2]), "+f"((d)[3]) \
        : "r"((a)[0]), "r"((a)[1]), "r"((a)[2]), "r"((a)[3]), "r"(b0), "r"(b1))

// ======================= B in mma-fragment order (GLOBAL, L1-hot) ===========
// Fragment table: [j=42 chunks][nt=3 n-tiles][lane=32][reg=2] u32 (bf16x2).
// K sections: j 0..13 = Chi, 14..27 = Clo, 28..41 = Chi (for the Xlo term).
__device__ uint32_t g_Bfrag[42 * 3 * 32 * 2];

__device__ __forceinline__ float fetch3(const float* __restrict__ b30,
                                        const float* __restrict__ b31,
                                        int i, int j, int k, int c){
    int base = ((i * 9 + j) * 9 + k) * 3;
    if (c < 3) return b30[base + c];
    return b31[base * 3 + (c - 3)];
}

__device__ float coef(int m, int n,
                      const float* b10, const float* b11,
                      const float* b20, const float* b21,
                      const float* b30, const float* b31){
    if (m >= 219 || n >= 24) return 0.0f;
    if (m < 9){                               // deg1 -> cols 0..3
        if (n >= 4) return 0.0f;
        return (n == 0) ? b10[m] : b11[m * 3 + (n - 1)];
    }
    if (m < 54){                              // deg2 -> cols 4..11
        if (n < 4 || n >= 12) return 0.0f;
        int m2 = m - 9, a = 0, rem = m2;
        while (rem >= 9 - a){ rem -= 9 - a; a++; }
        int b = a + rem;
        int c2 = n - 4;
        float v;
        if (c2 < 2){
            v = b20[(a * 9 + b) * 2 + c2];
            if (a != b) v += b20[(b * 9 + a) * 2 + c2];
        } else {
            int sp = c2 - 2;
            v = b21[(a * 9 + b) * 6 + sp];
            if (a != b) v += b21[(b * 9 + a) * 6 + sp];
        }
        return v;
    }
    if (n < 12) return 0.0f;                  // deg3 -> cols 12..23
    int m3 = m - 54, a = 0, rem = m3;
    while (true){ int cnt = (9 - a) * (10 - a) / 2; if (rem < cnt) break; rem -= cnt; a++; }
    int b = a;
    while (rem >= 9 - b){ rem -= 9 - b; b++; }
    int kk = b + rem;
    int c3 = n - 12;
    float v = fetch3(b30, b31, a, b, kk, c3);
    if (a == b && b == kk){
    } else if (a == b){
        v += fetch3(b30, b31, a, kk, b, c3) + fetch3(b30, b31, kk, a, b, c3);
    } else if (b == kk){
        v += fetch3(b30, b31, b, a, kk, c3) + fetch3(b30, b31, b, kk, a, c3);
    } else {
        v += fetch3(b30, b31, a, kk, b, c3) + fetch3(b30, b31, b, a, kk, c3)
           + fetch3(b30, b31, b, kk, a, c3) + fetch3(b30, b31, kk, a, b, c3)
           + fetch3(b30, b31, kk, b, a, c3);
    }
    return v;
}

__global__ void prep_kernel(const float* __restrict__ b10, const float* __restrict__ b11,
                            const float* __restrict__ b20, const float* __restrict__ b21,
                            const float* __restrict__ b30, const float* __restrict__ b31){
    int id = blockIdx.x * blockDim.x + threadIdx.x;
    if (id >= 42 * 3 * 32 * 2) return;
    int reg  = id & 1;
    int lane = (id >> 1) & 31;
    int ntj  = id >> 6;
    int nt   = ntj % 3;
    int j    = ntj / 3;
    int sec  = j / 14;
    int kb   = (j - sec * 14) * 16;
    int n    = nt * 8 + (lane >> 2);
    int m0   = kb + (lane & 3) * 2 + reg * 8;

    float c0 = coef(m0,     n, b10, b11, b20, b21, b30, b31);
    float c1 = coef(m0 + 1, n, b10, b11, b20, b21, b30, b31);
    if (sec == 1){   // Clo section: residual after bf16 rounding
        c0 = c0 - __bfloat162float(__float2bfloat16_rn(c0));
        c1 = c1 - __bfloat162float(__float2bfloat16_rn(c1));
    }
    g_Bfrag[id] = packbf(c0, c1);
}

// ======================= main kernel: 1 block = 1 node, 256 threads =========
// X buffer: 128 rows x 896B (hi bf16 cols 0..223 = groups 0..27, lo groups
// 28..55), 16B groups XOR-swizzled by (g ^ (row&7)) -> conflict-free STS.128
// and ldmatrix with NO padding (112 KB -> 2 blocks/SM).
// Phase 1: threads 0-127 stage Xhi, threads 128-255 stage Xlo IN PARALLEL.
// Phase 2: 8 warps x 1 m-tile x 3 n-tiles x 42 K-chunks of mma.sync;
//          B fragments read straight from global (L1-hot across 2048 blocks).
// Phase 3: D -> smem moments -> per-channel weight fold.
__global__ void __launch_bounds__(256) mace_kernel(
    const float* __restrict__ nf, const int* __restrict__ species,
    const float* __restrict__ w10, const float* __restrict__ w11,
    const float* __restrict__ w20, const float* __restrict__ w21,
    const float* __restrict__ w30, const float* __restrict__ w31,
    float* __restrict__ out)
{
    extern __shared__ __align__(16) char smX[];   // 128 * 896 = 114688 B
    const uint32_t xb_u32 = smem_to_u32(smX);

    const int tid  = threadIdx.x;
    const int node = blockIdx.x;

    // ---- phase 1: monomials -> swizzled smem (hi by t<128, lo by t>=128) ----
    {
        const int  ch   = tid & 127;
        const bool isLo = tid >= 128;
        const float* nfp = nf + (size_t)node * 1152;
        float xv[9];
        xv[0] = nfp[ch];
        #pragma unroll
        for (int j = 0; j < 3; j++) xv[1 + j] = nfp[128 + ch * 3 + j];
        #pragma unroll
        for (int j = 0; j < 5; j++) xv[4 + j] = nfp[512 + ch * 5 + j];

        char* rowp = smX + (size_t)ch * 896;
        const int gadd = isLo ? 28 : 0;
        const int sw   = ch & 7;
        uint32_t buf[4];
        float stash = 0.f;
        int s = 0;
        auto emit = [&](float v){
            float val = v;
            if (isLo) val = v - __bfloat162float(__float2bfloat16_rn(v));
            if (s & 1) buf[(s & 7) >> 1] = packbf(stash, val); else stash = val;
            if ((s & 7) == 7){
                int g = (s >> 3) + gadd;
                *(uint4*)(rowp + (uint32_t)((g ^ sw) * 16)) =
                    make_uint4(buf[0], buf[1], buf[2], buf[3]);
            }
            s++;
        };
        #pragma unroll
        for (int a = 0; a < 9; a++) emit(xv[a]);
        #pragma unroll
        for (int a = 0; a < 9; a++)
            #pragma unroll
            for (int b = a; b < 9; b++) emit(xv[a] * xv[b]);
        #pragma unroll
        for (int a = 0; a < 9; a++)
            #pragma unroll
            for (int b = a; b < 9; b++){
                float pab = xv[a] * xv[b];
                #pragma unroll
                for (int k = b; k < 9; k++) emit(pab * xv[k]);
            }
        #pragma unroll
        for (int z = 0; z < 5; z++) emit(0.0f);   // pad 219 -> 224 cols
    }
    __syncthreads();

    // ---- phase 2: tensor-core contraction (8 warps x 1 m-tile) ----
    const int lane = tid & 31;
    const int wrp  = tid >> 5;          // 0..7 -> m-tile (16 rows each)
    const int r    = wrp * 16 + (lane & 15);
    const int gofs = lane >> 4;         // column-group offset within chunk
    const uint32_t rbase = xb_u32 + (uint32_t)r * 896u;
    const int rsw = r & 7;

    float d[3][4];
    #pragma unroll
    for (int nt = 0; nt < 3; nt++)
        #pragma unroll
        for (int q = 0; q < 4; q++) d[nt][q] = 0.0f;

    const u64* __restrict__ bfr = (const u64*)g_Bfrag;

    for (int j = 0; j < 42; j++){
        int sec   = j / 14;
        int gbase = (j - sec * 14) * 2 + (sec == 2 ? 28 : 0);
        int g     = gbase + gofs;
        uint32_t ad = rbase + (uint32_t)((g ^ rsw) * 16);
        uint32_t a0[4];
        LDSM_X4(a0, ad);
        #pragma unroll
        for (int nt = 0; nt < 3; nt++){
            u64 bv = bfr[(j * 3 + nt) * 32 + lane];
            uint32_t b0 = (uint32_t)bv, b1 = (uint32_t)(bv >> 32);
            MMA16816(d[nt], a0, b0, b1);
        }
    }
    __syncthreads();

    // ---- phase 3a: D fragments -> moments buffer (reuse X region) ----
    float* mom = (float*)smX;   // [128][24]
    {
        int r0 = wrp * 16 + (lane >> 2);
        int c0 = (lane & 3) * 2;
        #pragma unroll
        for (int nt = 0; nt < 3; nt++){
            int cc = nt * 8 + c0;
            mom[r0 * 24 + cc]           = d[nt][0];
            mom[r0 * 24 + cc + 1]       = d[nt][1];
            mom[(r0 + 8) * 24 + cc]     = d[nt][2];
            mom[(r0 + 8) * 24 + cc + 1] = d[nt][3];
        }
    }
    __syncthreads();

    // ---- phase 3b: per-channel weight fold (threads 0..127) ----
    if (tid < 128){
        const int ch = tid;
        const int sp = species[node];
        float M[24];
        #pragma unroll
        for (int i = 0; i < 6; i++){
            float4 v = ((const float4*)(mom + ch * 24))[i];
            M[i * 4 + 0] = v.x; M[i * 4 + 1] = v.y;
            M[i * 4 + 2] = v.z; M[i * 4 + 3] = v.w;
        }
        float* outp = out + (size_t)node * 512;
        outp[ch] = w10[sp * 128 + ch]       * M[0]
                 + w20[sp * 256 + ch]       * M[4]
                 + w20[sp * 256 + 128 + ch] * M[5]
                 + w30[sp * 384 + ch]       * M[12]
                 + w30[sp * 384 + 128 + ch] * M[13]
                 + w30[sp * 384 + 256 + ch] * M[14];

        float w11v = w11[sp * 128 + ch];
        float w21a = w21[sp * 256 + ch],      w21b = w21[sp * 256 + 128 + ch];
        float w31a = w31[sp * 384 + ch],      w31b = w31[sp * 384 + 128 + ch];
        float w31c = w31[sp * 384 + 256 + ch];
        #pragma unroll
        for (int p = 0; p < 3; p++){
            outp[128 + ch * 3 + p] = w11v * M[1 + p]
                                   + w21a * M[6 + p]  + w21b * M[9 + p]
                                   + w31a * M[15 + p] + w31b * M[18 + p]
                                   + w31c * M[21 + p];
        }
    }
}

extern "C" void kernel_launch(void* const* d_in, const int* in_sizes, int n_in,
                              void* d_out, int out_size){
    // metadata order is INTERLEAVED (b_i, w_i) pairs.
    const float* nf      = (const float*)d_in[0];
    const int*   species = (const int*)  d_in[1];
    const float* b10 = (const float*)d_in[2];
    const float* w10 = (const float*)d_in[3];
    const float* b11 = (const float*)d_in[4];
    const float* w11 = (const float*)d_in[5];
    const float* b20 = (const float*)d_in[6];
    const float* w20 = (const float*)d_in[7];
    const float* b21 = (const float*)d_in[8];
    const float* w21 = (const float*)d_in[9];
    const float* b30 = (const float*)d_in[10];
    const float* w30 = (const float*)d_in[11];
    const float* b31 = (const float*)d_in[12];
    const float* w31 = (const float*)d_in[13];

    const int n_nodes = in_sizes[1];   // 2048

    const int smem_bytes = 128 * 896;  // 114688 B -> 2 blocks/SM
    cudaFuncSetAttribute(mace_kernel,
                         cudaFuncAttributeMaxDynamicSharedMemorySize, smem_bytes);

    // build B fragment table (hi/lo compensated, mma fragment order)
    prep_kernel<<<63, 128>>>(b10, b11, b20, b21, b30, b31);
    // per-node tensor-core contraction
    mace_kernel<<<n_nodes, 256, smem_bytes>>>(nf, species,
                                              w10, w11, w20, w21, w30, w31,
                                              (float*)d_out);
}

// round 17
// speedup vs baseline: 3.8866x; 1.4948x over previous
#include <cuda_runtime.h>
#include <cuda_bf16.h>
#include <cstdint>

typedef unsigned long long u64;

__device__ __forceinline__ uint32_t packbf(float lo, float hi){
    uint32_t r;
    asm("cvt.rn.bf16x2.f32 %0, %2, %1;" : "=r"(r) : "f"(lo), "f"(hi));
    return r;
}
__device__ __forceinline__ uint32_t smem_to_u32(const void* p){
    uint32_t a;
    asm("{ .reg .u64 t; cvta.to.shared.u64 t, %1; cvt.u32.u64 %0, t; }"
        : "=r"(a) : "l"(p));
    return a;
}
#define LDSM_X4(r, addr) \
    asm volatile("ldmatrix.sync.aligned.m8n8.x4.shared.b16 {%0,%1,%2,%3}, [%4];" \
        : "=r"((r)[0]), "=r"((r)[1]), "=r"((r)[2]), "=r"((r)[3]) : "r"(addr))
#define MMA16816(d, a, b0, b1) \
    asm volatile("mma.sync.aligned.m16n8k16.row.col.f32.bf16.bf16.f32 " \
        "{%0,%1,%2,%3}, {%4,%5,%6,%7}, {%8,%9}, {%0,%1,%2,%3};" \
        : "+f"((d)[0]), "+f"((d)[1]), "+f"((d)[2]), "+f"((d)[3]) \
        : "r"((a)[0]), "r"((a)[1]), "r"((a)[2]), "r"((a)[3]), "r"(b0), "r"(b1))

// ======================= B in mma-fragment order (GLOBAL, L1-hot) ===========
// [j=42 chunks][nt=3][lane=32][reg=2] u32 bf16x2.
// Sections: j 0..13 = Chi, 14..27 = Clo, 28..41 = Chi (for the Xlo term).
__device__ uint32_t g_Bfrag[42 * 3 * 32 * 2];

__device__ __forceinline__ float fetch3(const float* __restrict__ b30,
                                        const float* __restrict__ b31,
                                        int i, int j, int k, int c){
    int base = ((i * 9 + j) * 9 + k) * 3;
    if (c < 3) return b30[base + c];
    return b31[base * 3 + (c - 3)];
}

__device__ float coef(int m, int n,
                      const float* b10, const float* b11,
                      const float* b20, const float* b21,
                      const float* b30, const float* b31){
    if (m >= 219 || n >= 24) return 0.0f;
    if (m < 9){
        if (n >= 4) return 0.0f;
        return (n == 0) ? b10[m] : b11[m * 3 + (n - 1)];
    }
    if (m < 54){
        if (n < 4 || n >= 12) return 0.0f;
        int m2 = m - 9, a = 0, rem = m2;
        while (rem >= 9 - a){ rem -= 9 - a; a++; }
        int b = a + rem;
        int c2 = n - 4;
        float v;
        if (c2 < 2){
            v = b20[(a * 9 + b) * 2 + c2];
            if (a != b) v += b20[(b * 9 + a) * 2 + c2];
        } else {
            int sp = c2 - 2;
            v = b21[(a * 9 + b) * 6 + sp];
            if (a != b) v += b21[(b * 9 + a) * 6 + sp];
        }
        return v;
    }
    if (n < 12) return 0.0f;
    int m3 = m - 54, a = 0, rem = m3;
    while (true){ int cnt = (9 - a) * (10 - a) / 2; if (rem < cnt) break; rem -= cnt; a++; }
    int b = a;
    while (rem >= 9 - b){ rem -= 9 - b; b++; }
    int kk = b + rem;
    int c3 = n - 12;
    float v = fetch3(b30, b31, a, b, kk, c3);
    if (a == b && b == kk){
    } else if (a == b){
        v += fetch3(b30, b31, a, kk, b, c3) + fetch3(b30, b31, kk, a, b, c3);
    } else if (b == kk){
        v += fetch3(b30, b31, b, a, kk, c3) + fetch3(b30, b31, b, kk, a, c3);
    } else {
        v += fetch3(b30, b31, a, kk, b, c3) + fetch3(b30, b31, b, a, kk, c3)
           + fetch3(b30, b31, b, kk, a, c3) + fetch3(b30, b31, kk, a, b, c3)
           + fetch3(b30, b31, kk, b, a, c3);
    }
    return v;
}

__global__ void prep_kernel(const float* __restrict__ b10, const float* __restrict__ b11,
                            const float* __restrict__ b20, const float* __restrict__ b21,
                            const float* __restrict__ b30, const float* __restrict__ b31){
    int id = blockIdx.x * blockDim.x + threadIdx.x;
    if (id >= 42 * 3 * 32 * 2) return;
    int reg  = id & 1;
    int lane = (id >> 1) & 31;
    int ntj  = id >> 6;
    int nt   = ntj % 3;
    int j    = ntj / 3;
    int sec  = j / 14;
    int kb   = (j - sec * 14) * 16;
    int n    = nt * 8 + (lane >> 2);
    int m0   = kb + (lane & 3) * 2 + reg * 8;

    float c0 = coef(m0,     n, b10, b11, b20, b21, b30, b31);
    float c1 = coef(m0 + 1, n, b10, b11, b20, b21, b30, b31);
    if (sec == 1){   // Clo: residual after RN bf16 rounding
        c0 = c0 - __bfloat162float(__float2bfloat16_rn(c0));
        c1 = c1 - __bfloat162float(__float2bfloat16_rn(c1));
    }
    g_Bfrag[id] = packbf(c0, c1);
}

// ======================= main kernel: 1 block = 1 node, 256 threads =========
// X: 128 rows x 896B, 16B groups XOR-swizzled by (g ^ (row&7)); hi groups
// 0..27, lo groups 28..55. Phase 1: t<128 stage Xhi (PRMT truncation pack),
// t>=128 stage Xlo (exact remainder, PRMT pack) IN PARALLEL — no F2FP cvts.
// Phase 2: warp w: mt2 = w&3 (rows mt2*32..+31, 2 m-tiles), khalf = w>>2
// (21 K-chunks each) -> each B LDG.64 feeds TWO MMAs. D partials of the two
// K-halves go to separate smem buffers; fold sums them.
__global__ void __launch_bounds__(256) mace_kernel(
    const float* __restrict__ nf, const int* __restrict__ species,
    const float* __restrict__ w10, const float* __restrict__ w11,
    const float* __restrict__ w20, const float* __restrict__ w21,
    const float* __restrict__ w30, const float* __restrict__ w31,
    float* __restrict__ out)
{
    extern __shared__ __align__(16) char smX[];   // 128 * 896 = 114688 B
    const uint32_t xb_u32 = smem_to_u32(smX);

    const int tid  = threadIdx.x;
    const int node = blockIdx.x;

    // ---- phase 1: monomials -> swizzled smem, PRMT-packed hi/lo ----
    {
        const int  ch   = tid & 127;
        const bool isLo = tid >= 128;
        const float* nfp = nf + (size_t)node * 1152;
        float xv[9];
        xv[0] = nfp[ch];
        #pragma unroll
        for (int j = 0; j < 3; j++) xv[1 + j] = nfp[128 + ch * 3 + j];
        #pragma unroll
        for (int j = 0; j < 5; j++) xv[4 + j] = nfp[512 + ch * 5 + j];

        char* rowp = smX + (size_t)ch * 896;
        const int gadd = isLo ? 28 : 0;
        const int sw   = ch & 7;
        uint32_t buf[4];
        uint32_t stashU = 0;
        int s = 0;
        auto emit = [&](float v){
            uint32_t u = __float_as_uint(v);
            uint32_t pv;
            if (isLo){
                float hiF = __uint_as_float(u & 0xFFFF0000u);
                pv = __float_as_uint(v - hiF);     // exact remainder
            } else {
                pv = u;                            // truncated bf16 via PRMT
            }
            if (s & 1) buf[(s & 7) >> 1] = __byte_perm(stashU, pv, 0x7632);
            else       stashU = pv;
            if ((s & 7) == 7){
                int g = (s >> 3) + gadd;
                *(uint4*)(rowp + (uint32_t)((g ^ sw) * 16)) =
                    make_uint4(buf[0], buf[1], buf[2], buf[3]);
            }
            s++;
        };
        #pragma unroll
        for (int a = 0; a < 9; a++) emit(xv[a]);
        #pragma unroll
        for (int a = 0; a < 9; a++)
            #pragma unroll
            for (int b = a; b < 9; b++) emit(xv[a] * xv[b]);
        #pragma unroll
        for (int a = 0; a < 9; a++)
            #pragma unroll
            for (int b = a; b < 9; b++){
                float pab = xv[a] * xv[b];
                #pragma unroll
                for (int k = b; k < 9; k++) emit(pab * xv[k]);
            }
        #pragma unroll
        for (int z = 0; z < 5; z++) emit(0.0f);   // pad 219 -> 224 cols
    }
    __syncthreads();

    // ---- phase 2: tensor cores; warp = (2 m-tiles, K-half) ----
    const int lane  = tid & 31;
    const int wrp   = tid >> 5;
    const int mt2   = wrp & 3;            // rows mt2*32 .. +31
    const int khalf = wrp >> 2;           // K-chunks khalf*21 .. +20

    float d[2][3][4];
    #pragma unroll
    for (int mt = 0; mt < 2; mt++)
        #pragma unroll
        for (int nt = 0; nt < 3; nt++)
            #pragma unroll
            for (int q = 0; q < 4; q++) d[mt][nt][q] = 0.0f;

    // A addresses: row r = mt2*32 + mt*16 + (lane&15), col group gofs = lane>>4
    const int r0   = mt2 * 32 + (lane & 15);
    const int gofs = lane >> 4;
    const uint32_t rb0 = xb_u32 + (uint32_t)r0 * 896u;
    const int sw0 = r0 & 7, sw1 = (r0 + 16) & 7;

    // B base: element index j*96 + nt*32 + lane, j = khalf*21 + jj
    const u64* __restrict__ bp = (const u64*)g_Bfrag + (size_t)khalf * 21 * 96 + lane;

    const int j0 = khalf * 21;
    #pragma unroll
    for (int jj = 0; jj < 21; jj++){
        int j     = j0 + jj;
        int sec   = j / 14;
        int g     = (j - sec * 14) * 2 + (sec == 2 ? 28 : 0) + gofs;
        uint32_t a0[4], a1[4];
        LDSM_X4(a0, rb0 + (uint32_t)((g ^ sw0) * 16));
        LDSM_X4(a1, rb0 + 16u * 896u + (uint32_t)((g ^ sw1) * 16));
        #pragma unroll
        for (int nt = 0; nt < 3; nt++){
            u64 bv = bp[jj * 96 + nt * 32];
            uint32_t b0 = (uint32_t)bv, b1 = (uint32_t)(bv >> 32);
            MMA16816(d[0][nt], a0, b0, b1);
            MMA16816(d[1][nt], a1, b0, b1);
        }
    }
    __syncthreads();

    // ---- phase 3a: D fragments -> per-K-half moment buffers ----
    float* mom = (float*)smX + (size_t)khalf * 3072;   // [2][128][24]
    {
        int rr = mt2 * 32 + (lane >> 2);
        int c0 = (lane & 3) * 2;
        #pragma unroll
        for (int mt = 0; mt < 2; mt++){
            int rbase = rr + mt * 16;
            #pragma unroll
            for (int nt = 0; nt < 3; nt++){
                int cc = nt * 8 + c0;
                mom[rbase * 24 + cc]           = d[mt][nt][0];
                mom[rbase * 24 + cc + 1]       = d[mt][nt][1];
                mom[(rbase + 8) * 24 + cc]     = d[mt][nt][2];
                mom[(rbase + 8) * 24 + cc + 1] = d[mt][nt][3];
            }
        }
    }
    __syncthreads();

    // ---- phase 3b: per-channel weight fold (threads 0..127) ----
    if (tid < 128){
        const int ch = tid;
        const int sp = species[node];
        const float* m0p = (const float*)smX + ch * 24;
        const float* m1p = (const float*)smX + 3072 + ch * 24;
        float M[24];
        #pragma unroll
        for (int i = 0; i < 6; i++){
            float4 v0 = ((const float4*)m0p)[i];
            float4 v1 = ((const float4*)m1p)[i];
            M[i * 4 + 0] = v0.x + v1.x;  M[i * 4 + 1] = v0.y + v1.y;
            M[i * 4 + 2] = v0.z + v1.z;  M[i * 4 + 3] = v0.w + v1.w;
        }
        float* outp = out + (size_t)node * 512;
        outp[ch] = w10[sp * 128 + ch]       * M[0]
                 + w20[sp * 256 + ch]       * M[4]
                 + w20[sp * 256 + 128 + ch] * M[5]
                 + w30[sp * 384 + ch]       * M[12]
                 + w30[sp * 384 + 128 + ch] * M[13]
                 + w30[sp * 384 + 256 + ch] * M[14];

        float w11v = w11[sp * 128 + ch];
        float w21a = w21[sp * 256 + ch],      w21b = w21[sp * 256 + 128 + ch];
        float w31a = w31[sp * 384 + ch],      w31b = w31[sp * 384 + 128 + ch];
        float w31c = w31[sp * 384 + 256 + ch];
        #pragma unroll
        for (int p = 0; p < 3; p++){
            outp[128 + ch * 3 + p] = w11v * M[1 + p]
                                   + w21a * M[6 + p]  + w21b * M[9 + p]
                                   + w31a * M[15 + p] + w31b * M[18 + p]
                                   + w31c * M[21 + p];
        }
    }
}

extern "C" void kernel_launch(void* const* d_in, const int* in_sizes, int n_in,
                              void* d_out, int out_size){
    // metadata order is INTERLEAVED (b_i, w_i) pairs.
    const float* nf      = (const float*)d_in[0];
    const int*   species = (const int*)  d_in[1];
    const float* b10 = (const float*)d_in[2];
    const float* w10 = (const float*)d_in[3];
    const float* b11 = (const float*)d_in[4];
    const float* w11 = (const float*)d_in[5];
    const float* b20 = (const float*)d_in[6];
    const float* w20 = (const float*)d_in[7];
    const float* b21 = (const float*)d_in[8];
    const float* w21 = (const float*)d_in[9];
    const float* b30 = (const float*)d_in[10];
    const float* w30 = (const float*)d_in[11];
    const float* b31 = (const float*)d_in[12];
    const float* w31 = (const float*)d_in[13];

    const int n_nodes = in_sizes[1];   // 2048

    const int smem_bytes = 128 * 896;  // 114688 B -> 2 blocks/SM
    cudaFuncSetAttribute(mace_kernel,
                         cudaFuncAttributeMaxDynamicSharedMemorySize, smem_bytes);

    prep_kernel<<<63, 128>>>(b10, b11, b20, b21, b30, b31);
    mace_kernel<<<n_nodes, 256, smem_bytes>>>(nf, species,
                                              w10, w11, w20, w21, w30, w31,
                                              (float*)d_out);
}